// round 10
// baseline (speedup 1.0000x reference)
#include <cuda_runtime.h>
#include <cuda_bf16.h>
#include <math.h>
#include <stdint.h>

typedef uint32_t u32;

// out = (1/sqrt(7)) * sum_{p=1..7} M^p / sqrt(V_p)
// Horner in W2 = M^2/8 with diagonal absorption (exact coefficients):
//   T2' = (M + a2*I) * W2 + b2*M
//   A3  = T2' + a3*I ;  T3' = A3*W2 + b3*M
//   A4  = T3' + a4*I ;  acc' = A4*W2 + b4*M ;  out = fo * acc'
// bf16 hi/lo split GEMMs (AhBh + AlBh + AhBl, fp32 accum) on mma.m16n8k16.
// Warp tile 16x64: accumulators chain into the next A operand (registers),
// B = W2 fixed after G1 => G2/G3/G4 barrier-free. 4 CTAs/SM (128-reg cap).
struct Cf { float k2, a2, b2, a3, b3, a4, b4, fo; };

#define P_MH 0u
#define P_ML 8192u
#define P_WH 16384u
#define P_WL 24576u
#define SMEM_TOTAL 32768

static __device__ __forceinline__ u32 s2u(const void* p) {
    u32 a;
    asm("{ .reg .u64 t; cvta.to.shared.u64 t, %1; cvt.u32.u64 %0, t; }"
        : "=r"(a) : "l"(p));
    return a;
}
static __device__ __forceinline__ void ldsm4(u32* r, u32 a) {
    asm volatile("ldmatrix.sync.aligned.m8n8.x4.shared.b16 {%0,%1,%2,%3},[%4];"
                 : "=r"(r[0]), "=r"(r[1]), "=r"(r[2]), "=r"(r[3]) : "r"(a));
}
static __device__ __forceinline__ void ldsm4t(u32* r, u32 a) {
    asm volatile("ldmatrix.sync.aligned.m8n8.x4.trans.shared.b16 {%0,%1,%2,%3},[%4];"
                 : "=r"(r[0]), "=r"(r[1]), "=r"(r[2]), "=r"(r[3]) : "r"(a));
}
static __device__ __forceinline__ void mma16816(float* c, const u32* a, const u32* b) {
    asm volatile(
        "mma.sync.aligned.m16n8k16.row.col.f32.bf16.bf16.f32 "
        "{%0,%1,%2,%3},{%4,%5,%6,%7},{%8,%9},{%0,%1,%2,%3};"
        : "+f"(c[0]), "+f"(c[1]), "+f"(c[2]), "+f"(c[3])
        : "r"(a[0]), "r"(a[1]), "r"(a[2]), "r"(a[3]), "r"(b[0]), "r"(b[1]));
}
static __device__ __forceinline__ void split2(float x0, float x1, u32& H, u32& L) {
    __nv_bfloat16 h0 = __float2bfloat16_rn(x0);
    __nv_bfloat16 h1 = __float2bfloat16_rn(x1);
    float r0 = x0 - __bfloat162float(h0);
    float r1 = x1 - __bfloat162float(h1);
    __nv_bfloat162 hh = __halves2bfloat162(h0, h1);
    __nv_bfloat162 ll = __halves2bfloat162(__float2bfloat16_rn(r0),
                                           __float2bfloat16_rn(r1));
    H = *reinterpret_cast<u32*>(&hh);
    L = *reinterpret_cast<u32*>(&ll);
}
static __device__ __forceinline__ float2 upk2(u32 v) {
    return __bfloat1622float2(*reinterpret_cast<__nv_bfloat162*>(&v));
}
// add alf onto diagonal elems inside an A-fragment register pair (a0 or a3)
static __device__ __forceinline__ void fixd(u32& h, u32& l, float alf, int g, int tg) {
    float2 vh = upk2(h), vl = upk2(l);
    float x0 = vh.x + vl.x + ((g == tg * 2)     ? alf : 0.f);
    float x1 = vh.y + vl.y + ((g == tg * 2 + 1) ? alf : 0.f);
    split2(x0, x1, h, l);
}

// acc[32] += A*B over K=64, D slab = rows [RW,RW+16) x cols [0,64).
// A from packed regs (aph/apl) if non-null, else ldsm from planes aH/aL
// (with +alf on diagonal at k-step dks). B from planes bH/bL.
static __device__ __forceinline__ void gemm16(
    float acc[32], u32 sb, const u32* aph, const u32* apl,
    u32 aH, u32 aL, u32 bH, u32 bL,
    int RW, int lane, float alf, int dks)
{
    const int sub = lane >> 3, l7 = lane & 7;
    const int g = lane >> 2, tg = lane & 3;
#pragma unroll
    for (int ks = 0; ks < 4; ks++) {
        u32 ah[4], al[4];
        if (aph) {
#pragma unroll
            for (int j = 0; j < 4; j++) {
                ah[j] = aph[ks * 4 + j];
                al[j] = apl[ks * 4 + j];
            }
        } else {
            int arow = RW + ((sub & 1) << 3) + l7;
            u32 ab = (u32)arow * 128u +
                     (((u32)(ks * 32 + ((sub >> 1) << 4))) ^ (u32)((arow & 7) << 4));
            ldsm4(ah, sb + aH + ab);
            ldsm4(al, sb + aL + ab);
            if (ks == dks) {
                fixd(ah[0], al[0], alf, g, tg);
                fixd(ah[3], al[3], alf, g, tg);
            }
        }
        const int krow = ks * 16 + ((sub & 1) << 3) + l7;
        const u32 kswz = (u32)((krow & 7) << 4);
#pragma unroll
        for (int half = 0; half < 2; half++) {
            u32 bh[8], bl[8];
#pragma unroll
            for (int np = 0; np < 2; np++) {
                u32 bb = (u32)krow * 128u +
                         (((u32)((half * 2 + np) * 32 + ((sub >> 1) << 4))) ^ kswz);
                ldsm4t(bh + np * 4, sb + bH + bb);
                ldsm4t(bl + np * 4, sb + bL + bb);
            }
#pragma unroll
            for (int nt = 0; nt < 4; nt++) {
                float* c = acc + (half * 4 + nt) * 4;
                mma16816(c, ah, bh + nt * 2);
                mma16816(c, al, bh + nt * 2);
                mma16816(c, ah, bl + nt * 2);
            }
        }
    }
}

// acc = b * M (M read from hi/lo planes at fragment positions; conflict-free)
static __device__ __forceinline__ void init_beta(float acc[32], const char* sm,
                                                 float b, int RW, int g, int tg)
{
#pragma unroll
    for (int nt = 0; nt < 8; nt++)
#pragma unroll
        for (int h = 0; h < 2; h++) {
            int r = RW + g + 8 * h;
            u32 off = (u32)r * 128u +
                      (((u32)(nt * 16 + tg * 4)) ^ (u32)((r & 7) << 4));
            u32 vh = *reinterpret_cast<const u32*>(sm + P_MH + off);
            u32 vl = *reinterpret_cast<const u32*>(sm + P_ML + off);
            float2 fh = upk2(vh), fl = upk2(vl);
            acc[nt * 4 + 2 * h]     = b * (fh.x + fl.x);
            acc[nt * 4 + 2 * h + 1] = b * (fh.y + fl.y);
        }
}
// acc diagonal += alf (diag of rows [RW,RW+16) lands in n-tiles 2w, 2w+1)
static __device__ __forceinline__ void diag_add(float acc[32], float alf,
                                                int warp, int g, int tg)
{
    if (tg == (g >> 1)) {
#pragma unroll
        for (int h = 0; h < 2; h++)
            acc[(2 * warp + h) * 4 + 2 * h + (g & 1)] += alf;
    }
}
// pack accumulators -> A-fragment regs (layouts coincide: a[i] = acc[2i..2i+1])
static __device__ __forceinline__ void pack32(const float* acc, u32* ph, u32* pl) {
#pragma unroll
    for (int i = 0; i < 16; i++) split2(acc[2 * i], acc[2 * i + 1], ph[i], pl[i]);
}

__global__ void __launch_bounds__(128, 4)
rede_w(const float* __restrict__ G, float* __restrict__ O, Cf cf)
{
    extern __shared__ __align__(128) char sm[];
    const u32 sb = s2u(sm);
    const int tid = threadIdx.x;
    const int warp = tid >> 5, lane = tid & 31;
    const int RW = warp * 16;
    const int g = lane >> 2, tg = lane & 3;

    const float* Gm = G + (size_t)blockIdx.x * 4096;
    float*       Om = O + (size_t)blockIdx.x * 4096;

    // ---- prologue: M -> bf16 hi/lo planes (swizzled) ----
    {
        const int row = tid >> 1;
        const int halfb = (tid & 1) * 64;
        const float* src = Gm + row * 64 + (tid & 1) * 32;
#pragma unroll
        for (int j = 0; j < 4; j++) {
            float4 a = *reinterpret_cast<const float4*>(src + j * 8);
            float4 b = *reinterpret_cast<const float4*>(src + j * 8 + 4);
            u32 h0, l0, h1, l1, h2, l2, h3, l3;
            split2(a.x, a.y, h0, l0);
            split2(a.z, a.w, h1, l1);
            split2(b.x, b.y, h2, l2);
            split2(b.z, b.w, h3, l3);
            u32 off = (u32)row * 128u +
                      ((u32)(halfb + j * 16) ^ (u32)((row & 7) << 4));
            *reinterpret_cast<uint4*>(sm + P_MH + off) = make_uint4(h0, h1, h2, h3);
            *reinterpret_cast<uint4*>(sm + P_ML + off) = make_uint4(l0, l1, l2, l3);
        }
    }
    __syncthreads();

    float acc[32];

    // ---- G1: W2 = k2 * M*M ----
#pragma unroll
    for (int i = 0; i < 32; i++) acc[i] = 0.f;
    gemm16(acc, sb, (const u32*)0, (const u32*)0,
           P_MH, P_ML, P_MH, P_ML, RW, lane, 0.f, -1);
#pragma unroll
    for (int nt = 0; nt < 8; nt++)
#pragma unroll
        for (int h = 0; h < 2; h++) {
            int r = RW + g + 8 * h;
            u32 off = (u32)r * 128u +
                      (((u32)(nt * 16 + tg * 4)) ^ (u32)((r & 7) << 4));
            u32 H, L;
            split2(cf.k2 * acc[nt * 4 + 2 * h], cf.k2 * acc[nt * 4 + 2 * h + 1], H, L);
            *reinterpret_cast<u32*>(sm + P_WH + off) = H;
            *reinterpret_cast<u32*>(sm + P_WL + off) = L;
        }
    __syncthreads();          // W2 visible to all warps; last barrier in kernel

    u32 aph[16], apl[16];

    // ---- G2: T2' = (M + a2*I)*W2 + b2*M ----
    init_beta(acc, sm, cf.b2, RW, g, tg);
    gemm16(acc, sb, (const u32*)0, (const u32*)0,
           P_MH, P_ML, P_WH, P_WL, RW, lane, cf.a2, warp);
    diag_add(acc, cf.a3, warp, g, tg);      // bake A3 = T2' + a3*I
    pack32(acc, aph, apl);

    // ---- G3: T3' = A3*W2 + b3*M ----
    init_beta(acc, sm, cf.b3, RW, g, tg);
    gemm16(acc, sb, aph, apl, 0u, 0u, P_WH, P_WL, RW, lane, 0.f, -1);
    diag_add(acc, cf.a4, warp, g, tg);      // bake A4 = T3' + a4*I
    pack32(acc, aph, apl);

    // ---- G4: acc' = A4*W2 + b4*M ; out = fo * acc' ----
    init_beta(acc, sm, cf.b4, RW, g, tg);
    gemm16(acc, sb, aph, apl, 0u, 0u, P_WH, P_WL, RW, lane, 0.f, -1);
#pragma unroll
    for (int nt = 0; nt < 8; nt++)
#pragma unroll
        for (int h = 0; h < 2; h++) {
            int r = RW + g + 8 * h;
            int c = nt * 8 + tg * 2;
            float2 v;
            v.x = cf.fo * acc[nt * 4 + 2 * h];
            v.y = cf.fo * acc[nt * 4 + 2 * h + 1];
            *reinterpret_cast<float2*>(Om + r * 64 + c) = v;
        }
}

extern "C" void kernel_launch(void* const* d_in, const int* in_sizes, int n_in,
                              void* d_out, int out_size)
{
    const float* M = (const float*)d_in[0];
    float* out = (float*)d_out;
    int nmat = in_sizes[0] / 4096;

    // Exact variances V_p of M^p entries at R=64 (from _D_PARMS), V_1 = 1.
    const double V1 = 1.0, V2 = 64.0, V3 = 4104.0, V4 = 263696.0;
    const double V5 = 17021060.0, V6 = 1104218816.0, V7 = 72260728960.0;
    const double g1 = sqrt(64.0 * V1 / V3);
    const double g2 = sqrt(64.0 * V2 / V4);
    const double g3 = sqrt(64.0 * V3 / V5);
    const double g4 = sqrt(64.0 * V4 / V6);
    const double g5 = sqrt(64.0 * V5 / V7);
    const double ggg = g1 * g3 * g5;

    Cf cf;
    cf.k2 = 0.125f;
    cf.a2 = (float)(g4 * g2 / ggg);
    cf.b2 = (float)(g3 * g1 / ggg);
    cf.a3 = (float)(g2 / ggg);
    cf.b3 = (float)(g1 / ggg);
    cf.a4 = (float)(1.0 / ggg);
    cf.b4 = (float)(1.0 / ggg);
    cf.fo = (float)(ggg / sqrt(7.0));

    cudaFuncSetAttribute(rede_w, cudaFuncAttributeMaxDynamicSharedMemorySize,
                         SMEM_TOTAL);
    rede_w<<<nmat, 128, SMEM_TOTAL>>>(M, out, cf);
}

// round 11
// speedup vs baseline: 1.0035x; 1.0035x over previous
#include <cuda_runtime.h>
#include <cuda_bf16.h>
#include <math.h>
#include <stdint.h>

typedef uint32_t u32;

// out = (1/sqrt(7)) * sum_{p=1..7} M^p / sqrt(V_p)
// Horner in W2 = M^2/8 with diagonal absorption (exact coefficients):
//   T2' = (M + a2*I) * W2 + b2*M
//   A3  = T2' + a3*I ;  T3' = A3*W2 + b3*M
//   A4  = T3' + a4*I ;  acc' = A4*W2 + b4*M ;  out = fo * acc'
// bf16 hi/lo split GEMMs (AhBh + AlBh + AhBl, fp32 accum) on mma.m16n8k16.
// Warp tile 16x64: accumulators chain into the next A operand (registers),
// B = W2 fixed after G1 => G2/G3/G4 barrier-free. 4 CTAs/SM (128-reg cap).
struct Cf { float k2, a2, b2, a3, b3, a4, b4, fo; };

#define P_MH 0u
#define P_ML 8192u
#define P_WH 16384u
#define P_WL 24576u
#define SMEM_TOTAL 32768

static __device__ __forceinline__ u32 s2u(const void* p) {
    u32 a;
    asm("{ .reg .u64 t; cvta.to.shared.u64 t, %1; cvt.u32.u64 %0, t; }"
        : "=r"(a) : "l"(p));
    return a;
}
static __device__ __forceinline__ void ldsm4(u32* r, u32 a) {
    asm volatile("ldmatrix.sync.aligned.m8n8.x4.shared.b16 {%0,%1,%2,%3},[%4];"
                 : "=r"(r[0]), "=r"(r[1]), "=r"(r[2]), "=r"(r[3]) : "r"(a));
}
static __device__ __forceinline__ void ldsm4t(u32* r, u32 a) {
    asm volatile("ldmatrix.sync.aligned.m8n8.x4.trans.shared.b16 {%0,%1,%2,%3},[%4];"
                 : "=r"(r[0]), "=r"(r[1]), "=r"(r[2]), "=r"(r[3]) : "r"(a));
}
static __device__ __forceinline__ void mma16816(float* c, const u32* a, const u32* b) {
    asm volatile(
        "mma.sync.aligned.m16n8k16.row.col.f32.bf16.bf16.f32 "
        "{%0,%1,%2,%3},{%4,%5,%6,%7},{%8,%9},{%0,%1,%2,%3};"
        : "+f"(c[0]), "+f"(c[1]), "+f"(c[2]), "+f"(c[3])
        : "r"(a[0]), "r"(a[1]), "r"(a[2]), "r"(a[3]), "r"(b[0]), "r"(b[1]));
}
static __device__ __forceinline__ void split2(float x0, float x1, u32& H, u32& L) {
    __nv_bfloat16 h0 = __float2bfloat16_rn(x0);
    __nv_bfloat16 h1 = __float2bfloat16_rn(x1);
    float r0 = x0 - __bfloat162float(h0);
    float r1 = x1 - __bfloat162float(h1);
    __nv_bfloat162 hh = __halves2bfloat162(h0, h1);
    __nv_bfloat162 ll = __halves2bfloat162(__float2bfloat16_rn(r0),
                                           __float2bfloat16_rn(r1));
    H = *reinterpret_cast<u32*>(&hh);
    L = *reinterpret_cast<u32*>(&ll);
}
static __device__ __forceinline__ float2 upk2(u32 v) {
    return __bfloat1622float2(*reinterpret_cast<__nv_bfloat162*>(&v));
}
// add alf onto diagonal elems inside an A-fragment register pair (a0 or a3)
static __device__ __forceinline__ void fixd(u32& h, u32& l, float alf, int g, int tg) {
    float2 vh = upk2(h), vl = upk2(l);
    float x0 = vh.x + vl.x + ((g == tg * 2)     ? alf : 0.f);
    float x1 = vh.y + vl.y + ((g == tg * 2 + 1) ? alf : 0.f);
    split2(x0, x1, h, l);
}

// acc[32] += A*B over K=64, D slab = rows [RW,RW+16) x cols [0,64).
// A from packed regs (aph/apl) if non-null, else ldsm from planes aH/aL
// (with +alf on diagonal at k-step dks). B from planes bH/bL.
static __device__ __forceinline__ void gemm16(
    float acc[32], u32 sb, const u32* aph, const u32* apl,
    u32 aH, u32 aL, u32 bH, u32 bL,
    int RW, int lane, float alf, int dks)
{
    const int sub = lane >> 3, l7 = lane & 7;
    const int g = lane >> 2, tg = lane & 3;
#pragma unroll
    for (int ks = 0; ks < 4; ks++) {
        u32 ah[4], al[4];
        if (aph) {
#pragma unroll
            for (int j = 0; j < 4; j++) {
                ah[j] = aph[ks * 4 + j];
                al[j] = apl[ks * 4 + j];
            }
        } else {
            int arow = RW + ((sub & 1) << 3) + l7;
            u32 ab = (u32)arow * 128u +
                     (((u32)(ks * 32 + ((sub >> 1) << 4))) ^ (u32)((arow & 7) << 4));
            ldsm4(ah, sb + aH + ab);
            ldsm4(al, sb + aL + ab);
            if (ks == dks) {
                fixd(ah[0], al[0], alf, g, tg);
                fixd(ah[3], al[3], alf, g, tg);
            }
        }
        const int krow = ks * 16 + ((sub & 1) << 3) + l7;
        const u32 kswz = (u32)((krow & 7) << 4);
#pragma unroll
        for (int half = 0; half < 2; half++) {
            u32 bh[8], bl[8];
#pragma unroll
            for (int np = 0; np < 2; np++) {
                u32 bb = (u32)krow * 128u +
                         (((u32)((half * 2 + np) * 32 + ((sub >> 1) << 4))) ^ kswz);
                ldsm4t(bh + np * 4, sb + bH + bb);
                ldsm4t(bl + np * 4, sb + bL + bb);
            }
#pragma unroll
            for (int nt = 0; nt < 4; nt++) {
                float* c = acc + (half * 4 + nt) * 4;
                mma16816(c, ah, bh + nt * 2);
                mma16816(c, al, bh + nt * 2);
                mma16816(c, ah, bl + nt * 2);
            }
        }
    }
}

// acc = b * M (M read from hi/lo planes at fragment positions; conflict-free)
static __device__ __forceinline__ void init_beta(float acc[32], const char* sm,
                                                 float b, int RW, int g, int tg)
{
#pragma unroll
    for (int nt = 0; nt < 8; nt++)
#pragma unroll
        for (int h = 0; h < 2; h++) {
            int r = RW + g + 8 * h;
            u32 off = (u32)r * 128u +
                      (((u32)(nt * 16 + tg * 4)) ^ (u32)((r & 7) << 4));
            u32 vh = *reinterpret_cast<const u32*>(sm + P_MH + off);
            u32 vl = *reinterpret_cast<const u32*>(sm + P_ML + off);
            float2 fh = upk2(vh), fl = upk2(vl);
            acc[nt * 4 + 2 * h]     = b * (fh.x + fl.x);
            acc[nt * 4 + 2 * h + 1] = b * (fh.y + fl.y);
        }
}
// acc diagonal += alf (diag of rows [RW,RW+16) lands in n-tiles 2w, 2w+1)
static __device__ __forceinline__ void diag_add(float acc[32], float alf,
                                                int warp, int g, int tg)
{
    if (tg == (g >> 1)) {
#pragma unroll
        for (int h = 0; h < 2; h++)
            acc[(2 * warp + h) * 4 + 2 * h + (g & 1)] += alf;
    }
}
// pack accumulators -> A-fragment regs (layouts coincide: a[i] = acc[2i..2i+1])
static __device__ __forceinline__ void pack32(const float* acc, u32* ph, u32* pl) {
#pragma unroll
    for (int i = 0; i < 16; i++) split2(acc[2 * i], acc[2 * i + 1], ph[i], pl[i]);
}

__global__ void __launch_bounds__(128, 4)
rede_w(const float* __restrict__ G, float* __restrict__ O, Cf cf)
{
    extern __shared__ __align__(128) char sm[];
    const u32 sb = s2u(sm);
    const int tid = threadIdx.x;
    const int warp = tid >> 5, lane = tid & 31;
    const int RW = warp * 16;
    const int g = lane >> 2, tg = lane & 3;

    const float* Gm = G + (size_t)blockIdx.x * 4096;
    float*       Om = O + (size_t)blockIdx.x * 4096;

    // ---- prologue: M -> bf16 hi/lo planes (swizzled) ----
    {
        const int row = tid >> 1;
        const int halfb = (tid & 1) * 64;
        const float* src = Gm + row * 64 + (tid & 1) * 32;
#pragma unroll
        for (int j = 0; j < 4; j++) {
            float4 a = *reinterpret_cast<const float4*>(src + j * 8);
            float4 b = *reinterpret_cast<const float4*>(src + j * 8 + 4);
            u32 h0, l0, h1, l1, h2, l2, h3, l3;
            split2(a.x, a.y, h0, l0);
            split2(a.z, a.w, h1, l1);
            split2(b.x, b.y, h2, l2);
            split2(b.z, b.w, h3, l3);
            u32 off = (u32)row * 128u +
                      ((u32)(halfb + j * 16) ^ (u32)((row & 7) << 4));
            *reinterpret_cast<uint4*>(sm + P_MH + off) = make_uint4(h0, h1, h2, h3);
            *reinterpret_cast<uint4*>(sm + P_ML + off) = make_uint4(l0, l1, l2, l3);
        }
    }
    __syncthreads();

    float acc[32];

    // ---- G1: W2 = k2 * M*M ----
#pragma unroll
    for (int i = 0; i < 32; i++) acc[i] = 0.f;
    gemm16(acc, sb, (const u32*)0, (const u32*)0,
           P_MH, P_ML, P_MH, P_ML, RW, lane, 0.f, -1);
#pragma unroll
    for (int nt = 0; nt < 8; nt++)
#pragma unroll
        for (int h = 0; h < 2; h++) {
            int r = RW + g + 8 * h;
            u32 off = (u32)r * 128u +
                      (((u32)(nt * 16 + tg * 4)) ^ (u32)((r & 7) << 4));
            u32 H, L;
            split2(cf.k2 * acc[nt * 4 + 2 * h], cf.k2 * acc[nt * 4 + 2 * h + 1], H, L);
            *reinterpret_cast<u32*>(sm + P_WH + off) = H;
            *reinterpret_cast<u32*>(sm + P_WL + off) = L;
        }
    __syncthreads();          // W2 visible to all warps; last barrier in kernel

    u32 aph[16], apl[16];

    // ---- G2: T2' = (M + a2*I)*W2 + b2*M ----
    init_beta(acc, sm, cf.b2, RW, g, tg);
    gemm16(acc, sb, (const u32*)0, (const u32*)0,
           P_MH, P_ML, P_WH, P_WL, RW, lane, cf.a2, warp);
    diag_add(acc, cf.a3, warp, g, tg);      // bake A3 = T2' + a3*I
    pack32(acc, aph, apl);

    // ---- G3: T3' = A3*W2 + b3*M ----
    init_beta(acc, sm, cf.b3, RW, g, tg);
    gemm16(acc, sb, aph, apl, 0u, 0u, P_WH, P_WL, RW, lane, 0.f, -1);
    diag_add(acc, cf.a4, warp, g, tg);      // bake A4 = T3' + a4*I
    pack32(acc, aph, apl);

    // ---- G4: acc' = A4*W2 + b4*M ; out = fo * acc' ----
    init_beta(acc, sm, cf.b4, RW, g, tg);
    gemm16(acc, sb, aph, apl, 0u, 0u, P_WH, P_WL, RW, lane, 0.f, -1);
#pragma unroll
    for (int nt = 0; nt < 8; nt++)
#pragma unroll
        for (int h = 0; h < 2; h++) {
            int r = RW + g + 8 * h;
            int c = nt * 8 + tg * 2;
            float2 v;
            v.x = cf.fo * acc[nt * 4 + 2 * h];
            v.y = cf.fo * acc[nt * 4 + 2 * h + 1];
            *reinterpret_cast<float2*>(Om + r * 64 + c) = v;
        }
}

extern "C" void kernel_launch(void* const* d_in, const int* in_sizes, int n_in,
                              void* d_out, int out_size)
{
    const float* M = (const float*)d_in[0];
    float* out = (float*)d_out;
    int nmat = in_sizes[0] / 4096;

    // Exact variances V_p of M^p entries at R=64 (from _D_PARMS), V_1 = 1.
    const double V1 = 1.0, V2 = 64.0, V3 = 4104.0, V4 = 263696.0;
    const double V5 = 17021060.0, V6 = 1104218816.0, V7 = 72260728960.0;
    const double g1 = sqrt(64.0 * V1 / V3);
    const double g2 = sqrt(64.0 * V2 / V4);
    const double g3 = sqrt(64.0 * V3 / V5);
    const double g4 = sqrt(64.0 * V4 / V6);
    const double g5 = sqrt(64.0 * V5 / V7);
    const double ggg = g1 * g3 * g5;

    Cf cf;
    cf.k2 = 0.125f;
    cf.a2 = (float)(g4 * g2 / ggg);
    cf.b2 = (float)(g3 * g1 / ggg);
    cf.a3 = (float)(g2 / ggg);
    cf.b3 = (float)(g1 / ggg);
    cf.a4 = (float)(1.0 / ggg);
    cf.b4 = (float)(1.0 / ggg);
    cf.fo = (float)(ggg / sqrt(7.0));

    cudaFuncSetAttribute(rede_w, cudaFuncAttributeMaxDynamicSharedMemorySize,
                         SMEM_TOTAL);
    rede_w<<<nmat, 128, SMEM_TOTAL>>>(M, out, cf);
}

// round 12
// speedup vs baseline: 1.0085x; 1.0050x over previous
#include <cuda_runtime.h>
#include <cuda_bf16.h>
#include <math.h>
#include <stdint.h>

typedef uint32_t u32;

// out = (1/sqrt(7)) * sum_{p=1..7} M^p / sqrt(V_p)
// Horner in W2 = M^2/8 with diagonal absorption (exact coefficients):
//   T2' = (M + a2*I) * W2 + b2*M
//   A3  = T2' + a3*I ;  T3' = A3*W2 + b3*M
//   A4  = T3' + a4*I ;  acc' = A4*W2 + b4*M ;  out = fo * acc'
// bf16 hi/lo split GEMMs (AhBh + AlBh + AhBl, fp32 accum) on mma.m16n8k16.
// Warp tile 16x64: accumulators chain into the next A operand (registers),
// B = W2 fixed after G1 => G2/G3/G4 barrier-free. 4 CTAs/SM (128-reg cap).
struct Cf { float k2, a2, b2, a3, b3, a4, b4, fo; };

#define P_MH 0u
#define P_ML 8192u
#define P_WH 16384u
#define P_WL 24576u
#define SMEM_TOTAL 32768

static __device__ __forceinline__ u32 s2u(const void* p) {
    u32 a;
    asm("{ .reg .u64 t; cvta.to.shared.u64 t, %1; cvt.u32.u64 %0, t; }"
        : "=r"(a) : "l"(p));
    return a;
}
static __device__ __forceinline__ void ldsm4(u32* r, u32 a) {
    asm volatile("ldmatrix.sync.aligned.m8n8.x4.shared.b16 {%0,%1,%2,%3},[%4];"
                 : "=r"(r[0]), "=r"(r[1]), "=r"(r[2]), "=r"(r[3]) : "r"(a));
}
static __device__ __forceinline__ void ldsm4t(u32* r, u32 a) {
    asm volatile("ldmatrix.sync.aligned.m8n8.x4.trans.shared.b16 {%0,%1,%2,%3},[%4];"
                 : "=r"(r[0]), "=r"(r[1]), "=r"(r[2]), "=r"(r[3]) : "r"(a));
}
static __device__ __forceinline__ void mma16816(float* c, const u32* a, const u32* b) {
    asm volatile(
        "mma.sync.aligned.m16n8k16.row.col.f32.bf16.bf16.f32 "
        "{%0,%1,%2,%3},{%4,%5,%6,%7},{%8,%9},{%0,%1,%2,%3};"
        : "+f"(c[0]), "+f"(c[1]), "+f"(c[2]), "+f"(c[3])
        : "r"(a[0]), "r"(a[1]), "r"(a[2]), "r"(a[3]), "r"(b[0]), "r"(b[1]));
}
static __device__ __forceinline__ void split2(float x0, float x1, u32& H, u32& L) {
    __nv_bfloat16 h0 = __float2bfloat16_rn(x0);
    __nv_bfloat16 h1 = __float2bfloat16_rn(x1);
    float r0 = x0 - __bfloat162float(h0);
    float r1 = x1 - __bfloat162float(h1);
    __nv_bfloat162 hh = __halves2bfloat162(h0, h1);
    __nv_bfloat162 ll = __halves2bfloat162(__float2bfloat16_rn(r0),
                                           __float2bfloat16_rn(r1));
    H = *reinterpret_cast<u32*>(&hh);
    L = *reinterpret_cast<u32*>(&ll);
}
static __device__ __forceinline__ float2 upk2(u32 v) {
    return __bfloat1622float2(*reinterpret_cast<__nv_bfloat162*>(&v));
}
// add alf onto diagonal elems inside an A-fragment register pair (a0 or a3)
static __device__ __forceinline__ void fixd(u32& h, u32& l, float alf, int g, int tg) {
    float2 vh = upk2(h), vl = upk2(l);
    float x0 = vh.x + vl.x + ((g == tg * 2)     ? alf : 0.f);
    float x1 = vh.y + vl.y + ((g == tg * 2 + 1) ? alf : 0.f);
    split2(x0, x1, h, l);
}

// acc[32] += A*B over K=64, D slab = rows [RW,RW+16) x cols [0,64).
// A from packed regs (aph/apl) if non-null, else ldsm from planes aH/aL
// (with +alf on diagonal at k-step dks). B from planes bH/bL.
static __device__ __forceinline__ void gemm16(
    float acc[32], u32 sb, const u32* aph, const u32* apl,
    u32 aH, u32 aL, u32 bH, u32 bL,
    int RW, int lane, float alf, int dks)
{
    const int sub = lane >> 3, l7 = lane & 7;
    const int g = lane >> 2, tg = lane & 3;
#pragma unroll
    for (int ks = 0; ks < 4; ks++) {
        u32 ah[4], al[4];
        if (aph) {
#pragma unroll
            for (int j = 0; j < 4; j++) {
                ah[j] = aph[ks * 4 + j];
                al[j] = apl[ks * 4 + j];
            }
        } else {
            int arow = RW + ((sub & 1) << 3) + l7;
            u32 ab = (u32)arow * 128u +
                     (((u32)(ks * 32 + ((sub >> 1) << 4))) ^ (u32)((arow & 7) << 4));
            ldsm4(ah, sb + aH + ab);
            ldsm4(al, sb + aL + ab);
            if (ks == dks) {
                fixd(ah[0], al[0], alf, g, tg);
                fixd(ah[3], al[3], alf, g, tg);
            }
        }
        const int krow = ks * 16 + ((sub & 1) << 3) + l7;
        const u32 kswz = (u32)((krow & 7) << 4);
#pragma unroll
        for (int half = 0; half < 2; half++) {
            u32 bh[8], bl[8];
#pragma unroll
            for (int np = 0; np < 2; np++) {
                u32 bb = (u32)krow * 128u +
                         (((u32)((half * 2 + np) * 32 + ((sub >> 1) << 4))) ^ kswz);
                ldsm4t(bh + np * 4, sb + bH + bb);
                ldsm4t(bl + np * 4, sb + bL + bb);
            }
#pragma unroll
            for (int nt = 0; nt < 4; nt++) {
                float* c = acc + (half * 4 + nt) * 4;
                mma16816(c, ah, bh + nt * 2);
                mma16816(c, al, bh + nt * 2);
                mma16816(c, ah, bl + nt * 2);
            }
        }
    }
}

// acc = b * M (M read from hi/lo planes at fragment positions; conflict-free)
static __device__ __forceinline__ void init_beta(float acc[32], const char* sm,
                                                 float b, int RW, int g, int tg)
{
#pragma unroll
    for (int nt = 0; nt < 8; nt++)
#pragma unroll
        for (int h = 0; h < 2; h++) {
            int r = RW + g + 8 * h;
            u32 off = (u32)r * 128u +
                      (((u32)(nt * 16 + tg * 4)) ^ (u32)((r & 7) << 4));
            u32 vh = *reinterpret_cast<const u32*>(sm + P_MH + off);
            u32 vl = *reinterpret_cast<const u32*>(sm + P_ML + off);
            float2 fh = upk2(vh), fl = upk2(vl);
            acc[nt * 4 + 2 * h]     = b * (fh.x + fl.x);
            acc[nt * 4 + 2 * h + 1] = b * (fh.y + fl.y);
        }
}
// acc diagonal += alf (diag of rows [RW,RW+16) lands in n-tiles 2w, 2w+1)
static __device__ __forceinline__ void diag_add(float acc[32], float alf,
                                                int warp, int g, int tg)
{
    if (tg == (g >> 1)) {
#pragma unroll
        for (int h = 0; h < 2; h++)
            acc[(2 * warp + h) * 4 + 2 * h + (g & 1)] += alf;
    }
}
// pack accumulators -> A-fragment regs (layouts coincide: a[i] = acc[2i..2i+1])
static __device__ __forceinline__ void pack32(const float* acc, u32* ph, u32* pl) {
#pragma unroll
    for (int i = 0; i < 16; i++) split2(acc[2 * i], acc[2 * i + 1], ph[i], pl[i]);
}

__global__ void __launch_bounds__(128, 4)
rede_w(const float* __restrict__ G, float* __restrict__ O, Cf cf)
{
    extern __shared__ __align__(128) char sm[];
    const u32 sb = s2u(sm);
    const int tid = threadIdx.x;
    const int warp = tid >> 5, lane = tid & 31;
    const int RW = warp * 16;
    const int g = lane >> 2, tg = lane & 3;

    const float* Gm = G + (size_t)blockIdx.x * 4096;
    float*       Om = O + (size_t)blockIdx.x * 4096;

    // ---- prologue: M -> bf16 hi/lo planes (swizzled) ----
    {
        const int row = tid >> 1;
        const int halfb = (tid & 1) * 64;
        const float* src = Gm + row * 64 + (tid & 1) * 32;
#pragma unroll
        for (int j = 0; j < 4; j++) {
            float4 a = *reinterpret_cast<const float4*>(src + j * 8);
            float4 b = *reinterpret_cast<const float4*>(src + j * 8 + 4);
            u32 h0, l0, h1, l1, h2, l2, h3, l3;
            split2(a.x, a.y, h0, l0);
            split2(a.z, a.w, h1, l1);
            split2(b.x, b.y, h2, l2);
            split2(b.z, b.w, h3, l3);
            u32 off = (u32)row * 128u +
                      ((u32)(halfb + j * 16) ^ (u32)((row & 7) << 4));
            *reinterpret_cast<uint4*>(sm + P_MH + off) = make_uint4(h0, h1, h2, h3);
            *reinterpret_cast<uint4*>(sm + P_ML + off) = make_uint4(l0, l1, l2, l3);
        }
    }
    __syncthreads();

    float acc[32];

    // ---- G1: W2 = k2 * M*M ----
#pragma unroll
    for (int i = 0; i < 32; i++) acc[i] = 0.f;
    gemm16(acc, sb, (const u32*)0, (const u32*)0,
           P_MH, P_ML, P_MH, P_ML, RW, lane, 0.f, -1);
#pragma unroll
    for (int nt = 0; nt < 8; nt++)
#pragma unroll
        for (int h = 0; h < 2; h++) {
            int r = RW + g + 8 * h;
            u32 off = (u32)r * 128u +
                      (((u32)(nt * 16 + tg * 4)) ^ (u32)((r & 7) << 4));
            u32 H, L;
            split2(cf.k2 * acc[nt * 4 + 2 * h], cf.k2 * acc[nt * 4 + 2 * h + 1], H, L);
            *reinterpret_cast<u32*>(sm + P_WH + off) = H;
            *reinterpret_cast<u32*>(sm + P_WL + off) = L;
        }
    __syncthreads();          // W2 visible to all warps; last barrier in kernel

    u32 aph[16], apl[16];

    // ---- G2: T2' = (M + a2*I)*W2 + b2*M ----
    init_beta(acc, sm, cf.b2, RW, g, tg);
    gemm16(acc, sb, (const u32*)0, (const u32*)0,
           P_MH, P_ML, P_WH, P_WL, RW, lane, cf.a2, warp);
    diag_add(acc, cf.a3, warp, g, tg);      // bake A3 = T2' + a3*I
    pack32(acc, aph, apl);

    // ---- G3: T3' = A3*W2 + b3*M ----
    init_beta(acc, sm, cf.b3, RW, g, tg);
    gemm16(acc, sb, aph, apl, 0u, 0u, P_WH, P_WL, RW, lane, 0.f, -1);
    diag_add(acc, cf.a4, warp, g, tg);      // bake A4 = T3' + a4*I
    pack32(acc, aph, apl);

    // ---- G4: acc' = A4*W2 + b4*M ; out = fo * acc' ----
    init_beta(acc, sm, cf.b4, RW, g, tg);
    gemm16(acc, sb, aph, apl, 0u, 0u, P_WH, P_WL, RW, lane, 0.f, -1);
#pragma unroll
    for (int nt = 0; nt < 8; nt++)
#pragma unroll
        for (int h = 0; h < 2; h++) {
            int r = RW + g + 8 * h;
            int c = nt * 8 + tg * 2;
            float2 v;
            v.x = cf.fo * acc[nt * 4 + 2 * h];
            v.y = cf.fo * acc[nt * 4 + 2 * h + 1];
            *reinterpret_cast<float2*>(Om + r * 64 + c) = v;
        }
}

extern "C" void kernel_launch(void* const* d_in, const int* in_sizes, int n_in,
                              void* d_out, int out_size)
{
    const float* M = (const float*)d_in[0];
    float* out = (float*)d_out;
    int nmat = in_sizes[0] / 4096;

    // Exact variances V_p of M^p entries at R=64 (from _D_PARMS), V_1 = 1.
    const double V1 = 1.0, V2 = 64.0, V3 = 4104.0, V4 = 263696.0;
    const double V5 = 17021060.0, V6 = 1104218816.0, V7 = 72260728960.0;
    const double g1 = sqrt(64.0 * V1 / V3);
    const double g2 = sqrt(64.0 * V2 / V4);
    const double g3 = sqrt(64.0 * V3 / V5);
    const double g4 = sqrt(64.0 * V4 / V6);
    const double g5 = sqrt(64.0 * V5 / V7);
    const double ggg = g1 * g3 * g5;

    Cf cf;
    cf.k2 = 0.125f;
    cf.a2 = (float)(g4 * g2 / ggg);
    cf.b2 = (float)(g3 * g1 / ggg);
    cf.a3 = (float)(g2 / ggg);
    cf.b3 = (float)(g1 / ggg);
    cf.a4 = (float)(1.0 / ggg);
    cf.b4 = (float)(1.0 / ggg);
    cf.fo = (float)(ggg / sqrt(7.0));

    cudaFuncSetAttribute(rede_w, cudaFuncAttributeMaxDynamicSharedMemorySize,
                         SMEM_TOTAL);
    rede_w<<<nmat, 128, SMEM_TOTAL>>>(M, out, cf);
}